// round 6
// baseline (speedup 1.0000x reference)
#include <cuda_runtime.h>
#include <cstdint>

#define NUM_LEVELS 16
#define LOG2_T 19
#define TABLE_SIZE (1u << LOG2_T)
#define TABLE_MASK (TABLE_SIZE - 1u)
#define P1 2654435761u
#define P2 805459861u

#define TPB 128
#define NBLOCKS (16 * 148)   // grid-resident: 16 CTAs x 148 SMs

// Grid-stride persistent kernel. TWO threads per (point,level) item: half h
// handles the y=iy+h pair of yz-combos. x-prime is 1 -> even-ix corner pair
// {ix, ix+1} = aligned table slots {2m,2m+1}: one float4 fetches both corners.
// Even ix: 2 LDG.128/thread. Odd ix: +2 asm-predicated LDG.64 (no BSSY).
// Avg 6 gather-wavefronts/item = the floor for this hash structure.
__global__ __launch_bounds__(TPB) void hashenc_kernel(
    const float* __restrict__ x,
    const float* __restrict__ tables,
    float* __restrict__ out,
    int N)
{
    const int stride = NBLOCKS * TPB;                 // multiple of 32
    const int total  = N * NUM_LEVELS * 2;            // half-items
    const int tid0   = blockIdx.x * TPB + threadIdx.x;
    const int iters  = (total + stride - 1) / stride; // uniform across all threads

    for (int it = 0; it < iters; ++it) {
        int t = tid0 + it * stride;
        bool valid = t < total;
        int tc = valid ? t : (total - 1);             // clamp: loads always in-range
        int half = tc & 1;
        int l = (tc >> 1) & 15;
        int p = tc >> 5;

        // 32 consecutive t -> one point per warp -> broadcast loads
        float x0 = x[p * 3 + 0];
        float x1 = x[p * 3 + 1];
        float x2 = x[p * 3 + 2];

        const float hi = 1.0f - 1e-6f;
        x0 = fminf(fmaxf((x0 + 1.0f) * 0.5f, 0.0f), hi);
        x1 = fminf(fmaxf((x1 + 1.0f) * 0.5f, 0.0f), hi);
        x2 = fminf(fmaxf((x2 + 1.0f) * 0.5f, 0.0f), hi);

        float res = (float)(16 << l);
        float s0 = x0 * res, s1 = x1 * res, s2 = x2 * res;
        float f0 = floorf(s0), f1 = floorf(s1), f2 = floorf(s2);
        float fx = s0 - f0, fy = s1 - f1, fz = s2 - f2;
        uint32_t ix = (uint32_t)(int)f0;
        uint32_t iy = (uint32_t)(int)f1;
        uint32_t iz = (uint32_t)(int)f2;

        // this thread's y coordinate: iy + half
        uint32_t ay = (iy + (uint32_t)half) * P1;
        uint32_t K0 = ay ^ (iz * P2) ^ (uint32_t)l;          // (y, z0)
        uint32_t K1 = ay ^ ((iz + 1u) * P2) ^ (uint32_t)l;   // (y, z1)

        const float2* __restrict__ tbl  = (const float2*)tables + (size_t)l * TABLE_SIZE;
        const float4* __restrict__ tbl4 = (const float4*)tbl;

        uint32_t oddu = ix & 1u;
        uint32_t ix1 = ix + 1u;

        uint32_t i00 = (ix ^ K0) & TABLE_MASK;
        uint32_t i01 = (ix ^ K1) & TABLE_MASK;

        // paired loads: float4 covering the aligned slot-pair containing idx0
        float4 q0 = __ldg(&tbl4[i00 >> 1]);
        float4 q1 = __ldg(&tbl4[i01 >> 1]);

        // odd-ix: (ix+1) corner not adjacent -> 2 predicated 8B gathers (asm,
        // pure @p predication, no BSSY/branch)
        float eo0x, eo0y, eo1x, eo1y;
        {
            const float2* a0 = &tbl[(ix1 ^ K0) & TABLE_MASK];
            const float2* a1 = &tbl[(ix1 ^ K1) & TABLE_MASK];
            asm("{\n\t"
                ".reg .pred p;\n\t"
                "setp.ne.u32 p, %4, 0;\n\t"
                "mov.f32 %0, 0f00000000;\n\t"
                "mov.f32 %1, 0f00000000;\n\t"
                "mov.f32 %2, 0f00000000;\n\t"
                "mov.f32 %3, 0f00000000;\n\t"
                "@p ld.global.nc.v2.f32 {%0, %1}, [%5];\n\t"
                "@p ld.global.nc.v2.f32 {%2, %3}, [%6];\n\t"
                "}"
                : "=f"(eo0x), "=f"(eo0y), "=f"(eo1x), "=f"(eo1y)
                : "r"(oddu), "l"(a0), "l"(a1));
        }

        float gx = 1.0f - fx, gz = 1.0f - fz;
        float wy = half ? fy : (1.0f - fy);
        float wA = wy * gz;      // (y, z0)
        float wB = wy * fz;      // (y, z1)

        bool odd = oddu != 0u;
        float o0 = 0.0f, o1 = 0.0f;
#define COMBINE(Q, EOX, EOY, I0, W)                              \
        {                                                        \
            bool sel = (I0 & 1u) != 0u;                          \
            float e0x = sel ? Q.z : Q.x;                         \
            float e0y = sel ? Q.w : Q.y;                         \
            float epx = sel ? Q.x : Q.z;                         \
            float epy = sel ? Q.y : Q.w;                         \
            float e4x = odd ? EOX : epx;                         \
            float e4y = odd ? EOY : epy;                         \
            o0 += (e0x * gx + e4x * fx) * W;                     \
            o1 += (e0y * gx + e4y * fx) * W;                     \
        }
        COMBINE(q0, eo0x, eo0y, i00, wA)
        COMBINE(q1, eo1x, eo1y, i01, wB)
#undef COMBINE

        // pair reduction: lanes (2k, 2k+1) hold the two y-halves of one item
        o0 += __shfl_xor_sync(0xFFFFFFFFu, o0, 1);
        o1 += __shfl_xor_sync(0xFFFFFFFFu, o1, 1);

        if (valid && half == 0) {
            float2* orow = (float2*)(out + (size_t)p * (NUM_LEVELS * 2));
            orow[l] = make_float2(o0, o1);
        }
    }
}

extern "C" void kernel_launch(void* const* d_in, const int* in_sizes, int n_in,
                              void* d_out, int out_size) {
    const float* x      = (const float*)d_in[0];
    const float* tables = (const float*)d_in[1];
    float* out          = (float*)d_out;
    int N = in_sizes[0] / 3;

    hashenc_kernel<<<NBLOCKS, TPB>>>(x, tables, out, N);
}

// round 7
// speedup vs baseline: 1.0726x; 1.0726x over previous
#include <cuda_runtime.h>
#include <cstdint>

#define NUM_LEVELS 16
#define LOG2_T 19
#define TABLE_SIZE (1u << LOG2_T)
#define TABLE_MASK (TABLE_SIZE - 1u)
#define P1 2654435761u
#define P2 805459861u

// TWO threads per (point, level) item (R5 structure — best operating point):
// half h handles the y=iy+h pair of yz-combos. x-prime is 1 -> even-ix corner
// pair {ix, ix+1} = aligned table slots {2m,2m+1}: one float4 fetches both.
// Even ix: 2 LDG.128/thread. Odd ix: +2 @p-predicated LDG.64 (no BSSY branch).
// Avg 6 gather-wavefronts/item = the floor for this hash structure.
__global__ __launch_bounds__(256) void hashenc_kernel(
    const float* __restrict__ x,
    const float* __restrict__ tables,
    float* __restrict__ out,
    int N)
{
    int t = blockIdx.x * blockDim.x + threadIdx.x;
    int item = t >> 1;
    int half = t & 1;
    if (item >= N * NUM_LEVELS) return;
    int p = item >> 4;          // point index
    int l = item & 15;          // level index

    // 32 consecutive threads cover one point (16 levels x 2 halves) -> broadcast
    float x0 = x[p * 3 + 0];
    float x1 = x[p * 3 + 1];
    float x2 = x[p * 3 + 2];

    const float hi = 1.0f - 1e-6f;
    x0 = fminf(fmaxf((x0 + 1.0f) * 0.5f, 0.0f), hi);
    x1 = fminf(fmaxf((x1 + 1.0f) * 0.5f, 0.0f), hi);
    x2 = fminf(fmaxf((x2 + 1.0f) * 0.5f, 0.0f), hi);

    float res = (float)(16 << l);
    float s0 = x0 * res, s1 = x1 * res, s2 = x2 * res;
    float f0 = floorf(s0), f1 = floorf(s1), f2 = floorf(s2);
    float fx = s0 - f0, fy = s1 - f1, fz = s2 - f2;
    uint32_t ix = (uint32_t)(int)f0;
    uint32_t iy = (uint32_t)(int)f1;
    uint32_t iz = (uint32_t)(int)f2;

    // this thread's y coordinate: iy + half
    uint32_t ay = (iy + (uint32_t)half) * P1;
    uint32_t K0 = ay ^ (iz * P2) ^ (uint32_t)l;          // (y, z0)
    uint32_t K1 = ay ^ ((iz + 1u) * P2) ^ (uint32_t)l;   // (y, z1)

    const float2* __restrict__ tbl  = (const float2*)tables + (size_t)l * TABLE_SIZE;
    const float4* __restrict__ tbl4 = (const float4*)tbl;

    uint32_t oddu = ix & 1u;
    uint32_t ix1 = ix + 1u;

    uint32_t i00 = (ix ^ K0) & TABLE_MASK;
    uint32_t i01 = (ix ^ K1) & TABLE_MASK;

    // paired loads: float4 covering the aligned slot-pair containing idx0
    float4 q0 = __ldg(&tbl4[i00 >> 1]);
    float4 q1 = __ldg(&tbl4[i01 >> 1]);

    // odd-ix lanes: (ix+1) corner not adjacent -> 2 predicated 8B gathers.
    // Pure @p predication (no BSSY/BSYNC divergence region).
    float eo0x, eo0y, eo1x, eo1y;
    {
        const float2* a0 = &tbl[(ix1 ^ K0) & TABLE_MASK];
        const float2* a1 = &tbl[(ix1 ^ K1) & TABLE_MASK];
        asm("{\n\t"
            ".reg .pred p;\n\t"
            "setp.ne.u32 p, %4, 0;\n\t"
            "mov.f32 %0, 0f00000000;\n\t"
            "mov.f32 %1, 0f00000000;\n\t"
            "mov.f32 %2, 0f00000000;\n\t"
            "mov.f32 %3, 0f00000000;\n\t"
            "@p ld.global.nc.v2.f32 {%0, %1}, [%5];\n\t"
            "@p ld.global.nc.v2.f32 {%2, %3}, [%6];\n\t"
            "}"
            : "=f"(eo0x), "=f"(eo0y), "=f"(eo1x), "=f"(eo1y)
            : "r"(oddu), "l"(a0), "l"(a1));
    }

    float gx = 1.0f - fx, gz = 1.0f - fz;
    float wy = half ? fy : (1.0f - fy);
    float wA = wy * gz;      // (y, z0)
    float wB = wy * fz;      // (y, z1)

    bool odd = oddu != 0u;
    float o0 = 0.0f, o1 = 0.0f;
#define COMBINE(Q, EOX, EOY, I0, W)                              \
    {                                                            \
        bool sel = (I0 & 1u) != 0u;                              \
        float e0x = sel ? Q.z : Q.x;                             \
        float e0y = sel ? Q.w : Q.y;                             \
        float epx = sel ? Q.x : Q.z;                             \
        float epy = sel ? Q.y : Q.w;                             \
        float e4x = odd ? EOX : epx;                             \
        float e4y = odd ? EOY : epy;                             \
        o0 += (e0x * gx + e4x * fx) * W;                         \
        o1 += (e0y * gx + e4y * fx) * W;                         \
    }
    COMBINE(q0, eo0x, eo0y, i00, wA)
    COMBINE(q1, eo1x, eo1y, i01, wB)
#undef COMBINE

    // pair reduction: lanes (2k, 2k+1) hold the two y-halves of one item
    o0 += __shfl_xor_sync(0xFFFFFFFFu, o0, 1);
    o1 += __shfl_xor_sync(0xFFFFFFFFu, o1, 1);

    if (half == 0) {
        float2* orow = (float2*)(out + (size_t)p * (NUM_LEVELS * 2));
        orow[l] = make_float2(o0, o1);
    }
}

extern "C" void kernel_launch(void* const* d_in, const int* in_sizes, int n_in,
                              void* d_out, int out_size) {
    const float* x      = (const float*)d_in[0];
    const float* tables = (const float*)d_in[1];
    float* out          = (float*)d_out;
    int N = in_sizes[0] / 3;

    long long total = (long long)N * NUM_LEVELS * 2;
    int threads = 256;
    int blocks = (int)((total + threads - 1) / threads);
    hashenc_kernel<<<blocks, threads>>>(x, tables, out, N);
}